// round 11
// baseline (speedup 1.0000x reference)
#include <cuda_runtime.h>
#include <cstdint>

// ParallelVarPatchEmbed, persistent tf32 mma.sync kernel, 512 threads =
// two independent 8-warp GEMM groups per CTA sharing one resident B.
// R11: B flat [128][256] (no pad) with paired-k permutation rotated by
// 8*(row&3) words (&255 wrap) -> conflict-free ld.shared.v2 fragments,
// PLUS 3-stage cp.async A ring per group (prefetch distance 2).

static constexpr int THREADS = 512;

static constexpr int BIAS_OFF = 0;
static constexpr int B_OFF    = 128;
static constexpr int A_OFF    = 128 + 128 * 256;       // 32896
static constexpr int SMEM_FLOATS = A_OFF + 6 * 4096;   // 57472
static constexpr int SMEM_BYTES  = SMEM_FLOATS * 4;    // 229888

__device__ __forceinline__ uint32_t smem_u32(const void* p) {
    uint32_t a;
    asm("{ .reg .u64 t; cvta.to.shared.u64 t, %1; cvt.u32.u64 %0, t; }" : "=r"(a) : "l"(p));
    return a;
}
__device__ __forceinline__ void cpasync16(uint32_t dst, const float* src) {
    asm volatile("cp.async.cg.shared.global [%0], [%1], 16;" :: "r"(dst), "l"(src) : "memory");
}
__device__ __forceinline__ void cpcommit() {
    asm volatile("cp.async.commit_group;" ::: "memory");
}
template <int N> __device__ __forceinline__ void cpwait() {
    asm volatile("cp.async.wait_group %0;" :: "n"(N) : "memory");
}
__device__ __forceinline__ void barg(int id) {
    asm volatile("bar.sync %0, 256;" :: "r"(id) : "memory");
}
__device__ __forceinline__ uint32_t f2tf32(float f) {
    uint32_t r;
    asm("cvt.rna.tf32.f32 %0, %1;" : "=r"(r) : "f"(f));
    return r;
}
__device__ __forceinline__ float lds_f(uint32_t addr) {
    float v;
    asm volatile("ld.shared.f32 %0, [%1];" : "=f"(v) : "r"(addr));
    return v;
}
__device__ __forceinline__ void lds_v2(uint32_t addr, uint32_t& v0, uint32_t& v1) {
    asm volatile("ld.shared.v2.b32 {%0, %1}, [%2];" : "=r"(v0), "=r"(v1) : "r"(addr));
}
__device__ __forceinline__ void mma8(float* c, const uint32_t* a, uint32_t b0, uint32_t b1) {
    asm volatile(
        "mma.sync.aligned.m16n8k8.row.col.f32.tf32.tf32.f32 "
        "{%0,%1,%2,%3}, {%4,%5,%6,%7}, {%8,%9}, {%0,%1,%2,%3};"
        : "+f"(c[0]), "+f"(c[1]), "+f"(c[2]), "+f"(c[3])
        : "r"(a[0]), "r"(a[1]), "r"(a[2]), "r"(a[3]), "r"(b0), "r"(b1));
}
// A swizzle: word = m*32 + (k ^ ((m&7)*4)) within a 128x32 tile
__device__ __forceinline__ int swi(int m, int k) {
    return m * 32 + (k ^ ((m & 7) * 4));
}
// JAX demotes int64->int32 silently; detect layout from first 32 bytes.
__device__ __forceinline__ int get_var(const int* __restrict__ p32, int v) {
    bool is64 = ((p32[1] | p32[3] | p32[5] | p32[7]) == 0);
    return is64 ? p32[2 * v] : p32[v];
}

__global__ __launch_bounds__(THREADS, 1)
void pve_mma_kernel(const float* __restrict__ x,
                    const int* __restrict__ in_vars,
                    const float* __restrict__ w,
                    const float* __restrict__ bias,
                    float* __restrict__ out)
{
    extern __shared__ float smf[];
    const uint32_t sbase = smem_u32(smf);

    const int tid  = threadIdx.x;
    const int wid  = tid >> 5;
    const int lane = tid & 31;
    const int qrow = lane >> 2;     // 0..7
    const int qcol = lane & 3;      // 0..3
    const int g    = wid >> 3;      // group 0/1
    const int gwid = wid & 7;
    const int gtid = tid & 255;
    const int m0   = (gwid >> 1) * 32;
    const int n0   = (gwid & 1) * 64;

    const int rg = blockIdx.x, v = blockIdx.y, bg = blockIdx.z;
    const int var = get_var(in_vars, v);

    const float* wbase = w + (size_t)var * (128 * 256);

    if (tid < 128) smf[BIAS_OFF + tid] = bias[var * 128 + tid];

    // ---- B prologue: W[var] -> tf32 -> flat [128][256], paired-k + row rotation ----
    // pos(k,e) = ((k>>3)*8 + (k&3)*2 + ((k>>2)&1) + 8*(e&3)) & 255
    #pragma unroll
    for (int i = 0; i < 16; i++) {
        int idx = tid + 512 * i;            // 0..8191 float4s
        int e   = idx >> 6;                 // 0..127
        int k4  = idx & 63;
        int k   = k4 * 4;
        float4 vsrc = *reinterpret_cast<const float4*>(wbase + (size_t)e * 256 + k4 * 4);
        float* row = smf + B_OFF + e * 256;
        int base = (k >> 3) * 8 + ((k >> 2) & 1) + 8 * (e & 3);
        row[(base + 0) & 255] = __uint_as_float(f2tf32(vsrc.x));
        row[(base + 2) & 255] = __uint_as_float(f2tf32(vsrc.y));
        row[(base + 4) & 255] = __uint_as_float(f2tf32(vsrc.z));
        row[(base + 6) & 255] = __uint_as_float(f2tf32(vsrc.w));
    }
    __syncthreads();   // B + bias visible to both groups

    // group-local A stream: batches bg*8 + g*4 + (0..3)
    auto xb = [&](int bi) {
        int b = bg * 8 + g * 4 + bi;
        return x + (size_t)(b * 8 + v) * (512 * 512) + (size_t)rg * 64 * 512;
    };
    const uint32_t aring = A_OFF + g * 3 * 4096;

    auto issueA = [&](int t) {
        const int bi = t >> 3, ch = t & 7;
        const float* xbase = xb(bi);
        const uint32_t abase = sbase + (aring + (t % 3) * 4096) * 4;
        #pragma unroll
        for (int i = 0; i < 4; i++) {
            int idx = gtid + 256 * i;       // 0..1023 float4s
            int rl = idx >> 7, c4 = idx & 127;
            int pr = rl >> 1, dp = rl & 1;
            int m  = pr * 32 + (c4 >> 2);
            int kl = dp * 16 + (c4 & 3) * 4;
            cpasync16(abase + swi(m, kl) * 4,
                      xbase + (size_t)(pr * 16 + ch * 2 + dp) * 512 + c4 * 4);
        }
        cpcommit();
    };

    // loop-invariant offsets
    uint32_t koff[4][2];                    // A swizzled k offsets (bytes)
    #pragma unroll
    for (int ks = 0; ks < 4; ks++) {
        koff[ks][0] = (uint32_t)(((ks * 8 + qcol)     ^ (qrow * 4)) * 4);
        koff[ks][1] = (uint32_t)(((ks * 8 + qcol + 4) ^ (qrow * 4)) * 4);
    }
    const uint32_t arow0 = (uint32_t)(m0 + qrow) * 128;
    // B: row base (bytes) and rotation-base word position
    const uint32_t bRow0   = (uint32_t)(B_OFF + (n0 + qrow) * 256) * 4;
    const uint32_t posbase = (uint32_t)(qcol * 2 + 8 * (qrow & 3));

    float acc[2][8][4];
    #pragma unroll
    for (int mf = 0; mf < 2; mf++)
        #pragma unroll
        for (int nf = 0; nf < 8; nf++)
            #pragma unroll
            for (int j = 0; j < 4; j++) acc[mf][nf][j] = 0.0f;

    issueA(0); issueA(1);

    #pragma unroll 1
    for (int t = 0; t < 32; t++) {
        if (t < 31) cpwait<1>();
        else        cpwait<0>();
        barg(g + 1);                 // chunk t visible; slot (t+2)%3 fully consumed
        if (t + 2 < 32) issueA(t + 2);

        const uint32_t aR0    = sbase + (aring + (t % 3) * 4096) * 4 + arow0;
        const uint32_t pos_c  = posbase + (uint32_t)(t & 7) * 32;
        const uint32_t bBase  = sbase + bRow0;

        #pragma unroll
        for (int ks = 0; ks < 4; ks++) {
            const uint32_t k0 = koff[ks][0], k1 = koff[ks][1];
            uint32_t a[2][4];
            #pragma unroll
            for (int mf = 0; mf < 2; mf++) {
                const uint32_t r0 = aR0 + (uint32_t)(mf * 16) * 128;
                a[mf][0] = f2tf32(lds_f(r0 + k0));
                a[mf][1] = f2tf32(lds_f(r0 + 8 * 128 + k0));
                a[mf][2] = f2tf32(lds_f(r0 + k1));
                a[mf][3] = f2tf32(lds_f(r0 + 8 * 128 + k1));
            }
            const uint32_t pos4 = ((pos_c + (uint32_t)(ks * 8)) & 255u) * 4;
            #pragma unroll
            for (int nf = 0; nf < 8; nf++) {
                uint32_t b0, b1;
                lds_v2(bBase + (uint32_t)(nf * 8) * 1024 + pos4, b0, b1);
                mma8(acc[0][nf], a[0], b0, b1);
                mma8(acc[1][nf], a[1], b0, b1);
            }
        }

        if ((t & 7) == 7) {
            const int b = bg * 8 + g * 4 + (t >> 3);
            float* obase = out + (((size_t)(b * 8 + v) * 1024) + (size_t)rg * 128) * 128;
            const float* bs = smf + BIAS_OFF;
            #pragma unroll
            for (int mf = 0; mf < 2; mf++) {
                const int r = m0 + mf * 16 + qrow;
                #pragma unroll
                for (int nf = 0; nf < 8; nf++) {
                    const int e0 = n0 + nf * 8 + qcol * 2;
                    float2 lo, hi;
                    lo.x = acc[mf][nf][0] + bs[e0];
                    lo.y = acc[mf][nf][1] + bs[e0 + 1];
                    hi.x = acc[mf][nf][2] + bs[e0];
                    hi.y = acc[mf][nf][3] + bs[e0 + 1];
                    *reinterpret_cast<float2*>(obase + (size_t)r * 128 + e0)       = lo;
                    *reinterpret_cast<float2*>(obase + (size_t)(r + 8) * 128 + e0) = hi;
                    acc[mf][nf][0] = 0.0f; acc[mf][nf][1] = 0.0f;
                    acc[mf][nf][2] = 0.0f; acc[mf][nf][3] = 0.0f;
                }
            }
        }
    }
}

extern "C" void kernel_launch(void* const* d_in, const int* in_sizes, int n_in,
                              void* d_out, int out_size)
{
    const float* x       = (const float*)d_in[0];
    const int*   in_vars = (const int*)d_in[1];
    const float* w       = (const float*)d_in[2];
    const float* bias    = (const float*)d_in[3];
    float*       out     = (float*)d_out;

    cudaFuncSetAttribute(pve_mma_kernel,
                         cudaFuncAttributeMaxDynamicSharedMemorySize, SMEM_BYTES);

    dim3 grid(8, 8, 2);    // (row group, V, batch group) -> 128 persistent CTAs
    pve_mma_kernel<<<grid, THREADS, SMEM_BYTES>>>(x, in_vars, w, bias, out);
}

// round 12
// speedup vs baseline: 1.1587x; 1.1587x over previous
#include <cuda_runtime.h>
#include <cstdint>

// ParallelVarPatchEmbed, persistent tf32 mma.sync kernel, 512 threads.
// R12: warp-PAIR decoupling. Each pair (2 warps, same 32 A-rows, n split 64/64)
// owns a private 2-stage cp.async A ring + 64-thread named barrier -> 8
// independent streams per CTA, no group-wide lockstep. B resident in the
// R10 paired-k pad-264 layout (ld.shared.v2 fragments, conflict-free).
// Grid: 8(rg) x 8(v) x 2(bg) = 128 persistent CTAs.
// Pair p (0..7): m-quarter pr=p&3 (rows pr*32..pr*32+31), batch set p>>2.
// Each pair: 4 batches x 8 K-chunks = 32 chunk-iterations, warp tile 32x64.

static constexpr int THREADS = 512;

static constexpr int BROW     = 264;                   // B row stride (pad 8)
static constexpr int BIAS_OFF = 0;
static constexpr int B_OFF    = 128;
static constexpr int A_OFF    = 128 + 128 * BROW;      // 33920
static constexpr int SMEM_FLOATS = A_OFF + 8 * 2 * 1024;   // 50304
static constexpr int SMEM_BYTES  = SMEM_FLOATS * 4;        // 201216

__device__ __forceinline__ uint32_t smem_u32(const void* p) {
    uint32_t a;
    asm("{ .reg .u64 t; cvta.to.shared.u64 t, %1; cvt.u32.u64 %0, t; }" : "=r"(a) : "l"(p));
    return a;
}
__device__ __forceinline__ void cpasync16(uint32_t dst, const float* src) {
    asm volatile("cp.async.cg.shared.global [%0], [%1], 16;" :: "r"(dst), "l"(src) : "memory");
}
__device__ __forceinline__ void cpcommit() {
    asm volatile("cp.async.commit_group;" ::: "memory");
}
template <int N> __device__ __forceinline__ void cpwait() {
    asm volatile("cp.async.wait_group %0;" :: "n"(N) : "memory");
}
__device__ __forceinline__ void barpair(int id) {
    asm volatile("bar.sync %0, 64;" :: "r"(id) : "memory");
}
__device__ __forceinline__ uint32_t f2tf32(float f) {
    uint32_t r;
    asm("cvt.rna.tf32.f32 %0, %1;" : "=r"(r) : "f"(f));
    return r;
}
__device__ __forceinline__ float lds_f(uint32_t addr) {
    float v;
    asm volatile("ld.shared.f32 %0, [%1];" : "=f"(v) : "r"(addr));
    return v;
}
__device__ __forceinline__ void lds_v2(uint32_t addr, uint32_t& v0, uint32_t& v1) {
    asm volatile("ld.shared.v2.b32 {%0, %1}, [%2];" : "=r"(v0), "=r"(v1) : "r"(addr));
}
__device__ __forceinline__ void mma8(float* c, const uint32_t* a, uint32_t b0, uint32_t b1) {
    asm volatile(
        "mma.sync.aligned.m16n8k8.row.col.f32.tf32.tf32.f32 "
        "{%0,%1,%2,%3}, {%4,%5,%6,%7}, {%8,%9}, {%0,%1,%2,%3};"
        : "+f"(c[0]), "+f"(c[1]), "+f"(c[2]), "+f"(c[3])
        : "r"(a[0]), "r"(a[1]), "r"(a[2]), "r"(a[3]), "r"(b0), "r"(b1));
}
// JAX demotes int64->int32 silently; detect layout from first 32 bytes.
__device__ __forceinline__ int get_var(const int* __restrict__ p32, int v) {
    bool is64 = ((p32[1] | p32[3] | p32[5] | p32[7]) == 0);
    return is64 ? p32[2 * v] : p32[v];
}

__global__ __launch_bounds__(THREADS, 1)
void pve_mma_kernel(const float* __restrict__ x,
                    const int* __restrict__ in_vars,
                    const float* __restrict__ w,
                    const float* __restrict__ bias,
                    float* __restrict__ out)
{
    extern __shared__ float smf[];
    const uint32_t sbase = smem_u32(smf);

    const int tid  = threadIdx.x;
    const int wid  = tid >> 5;
    const int lane = tid & 31;
    const int qrow = lane >> 2;     // 0..7
    const int qcol = lane & 3;      // 0..3
    const int pair = wid >> 1;      // 0..7
    const int wpos = wid & 1;       // n-half
    const int pr   = pair & 3;      // m-quarter (patch row group)
    const int bset = pair >> 2;     // batch half within bg
    const int ptid = wpos * 32 + lane;   // 0..63 within pair
    const int n0   = wpos * 64;

    const int rg = blockIdx.x, v = blockIdx.y, bg = blockIdx.z;
    const int var = get_var(in_vars, v);

    const float* wbase = w + (size_t)var * (128 * 256);

    if (tid < 128) smf[BIAS_OFF + tid] = bias[var * 128 + tid];

    // ---- B prologue (all threads): W[var] -> tf32 -> flat [128][264] paired-k ----
    #pragma unroll
    for (int i = 0; i < 16; i++) {
        int idx = tid + 512 * i;            // 0..8191 float4s
        int e   = idx >> 6;                 // 0..127
        int k4  = idx & 63;
        int k   = k4 * 4;
        float4 vsrc = *reinterpret_cast<const float4*>(wbase + (size_t)e * 256 + k4 * 4);
        float* row = smf + B_OFF + e * BROW;
        int base = (k >> 3) * 8 + ((k >> 2) & 1);
        row[base + 0] = __uint_as_float(f2tf32(vsrc.x));
        row[base + 2] = __uint_as_float(f2tf32(vsrc.y));
        row[base + 4] = __uint_as_float(f2tf32(vsrc.z));
        row[base + 6] = __uint_as_float(f2tf32(vsrc.w));
    }
    __syncthreads();   // last CTA-wide barrier; pairs run free after this

    // ---- per-thread invariant copy mapping (4 x 16B per chunk) ----
    // idx = ptid + 64*i -> dp = idx>>7, c4 = idx&127, m' = c4>>2, kl = dp*16+(c4&3)*4
    uint32_t dst_inv[4];  // swizzled word offset within 1024-float stage
    int      src_inv[4];  // float offset relative to (pr,ch) row base
    #pragma unroll
    for (int i = 0; i < 4; i++) {
        int idx = ptid + 64 * i;
        int dp  = idx >> 7, c4 = idx & 127;
        int mp  = c4 >> 2;
        int kl  = dp * 16 + (c4 & 3) * 4;
        dst_inv[i] = (uint32_t)(mp * 32 + (kl ^ ((mp & 7) * 4)));
        src_inv[i] = dp * 512 + c4 * 4;
    }

    // pair's A ring base (floats)
    const uint32_t apair = (uint32_t)(A_OFF + pair * 2048);
    // x base for batch bi of this pair (pr rows already folded in)
    const float* xpr[4];
    #pragma unroll
    for (int bi = 0; bi < 4; bi++) {
        int b = bg * 8 + bset * 4 + bi;
        xpr[bi] = x + (size_t)(b * 8 + v) * (512 * 512)
                    + (size_t)(rg * 64 + pr * 16) * 512;
    }

    auto issueA = [&](int t) {
        const float* src = xpr[t >> 3] + (t & 7) * 1024;   // ch*2 image rows
        const uint32_t abase = sbase + (apair + (uint32_t)((t & 1) * 1024)) * 4;
        #pragma unroll
        for (int i = 0; i < 4; i++)
            cpasync16(abase + dst_inv[i] * 4, src + src_inv[i]);
        cpcommit();
    };

    // loop-invariant fragment offsets
    uint32_t koff[4][2];
    #pragma unroll
    for (int ks = 0; ks < 4; ks++) {
        koff[ks][0] = (uint32_t)(((ks * 8 + qcol)     ^ (qrow * 4)) * 4);
        koff[ks][1] = (uint32_t)(((ks * 8 + qcol + 4) ^ (qrow * 4)) * 4);
    }
    const uint32_t arow0  = (uint32_t)qrow * 128;                         // local row bytes
    const uint32_t bfrag0 = (uint32_t)(B_OFF + (n0 + qrow) * BROW + qcol * 2) * 4;

    float acc[2][8][4];
    #pragma unroll
    for (int mf = 0; mf < 2; mf++)
        #pragma unroll
        for (int nf = 0; nf < 8; nf++)
            #pragma unroll
            for (int j = 0; j < 4; j++) acc[mf][nf][j] = 0.0f;

    issueA(0);

    #pragma unroll 1
    for (int t = 0; t < 32; t++) {
        cpwait<0>();
        barpair(pair + 1);           // both warps: chunk t visible, old slot consumed
        if (t + 1 < 32) issueA(t + 1);

        const uint32_t aR0 = sbase + (apair + (uint32_t)((t & 1) * 1024)) * 4 + arow0;
        const uint32_t bR0 = sbase + bfrag0 + (uint32_t)(t & 7) * 128;

        #pragma unroll
        for (int ks = 0; ks < 4; ks++) {
            const uint32_t k0 = koff[ks][0], k1 = koff[ks][1];
            uint32_t a[2][4];
            #pragma unroll
            for (int mf = 0; mf < 2; mf++) {
                const uint32_t r0 = aR0 + (uint32_t)(mf * 16) * 128;
                a[mf][0] = f2tf32(lds_f(r0 + k0));
                a[mf][1] = f2tf32(lds_f(r0 + 8 * 128 + k0));
                a[mf][2] = f2tf32(lds_f(r0 + k1));
                a[mf][3] = f2tf32(lds_f(r0 + 8 * 128 + k1));
            }
            const uint32_t bks = bR0 + (uint32_t)(ks * 32);
            #pragma unroll
            for (int nf = 0; nf < 8; nf++) {
                uint32_t b0, b1;
                lds_v2(bks + (uint32_t)(nf * 8) * (BROW * 4), b0, b1);
                mma8(acc[0][nf], a[0], b0, b1);
                mma8(acc[1][nf], a[1], b0, b1);
            }
        }

        if ((t & 7) == 7) {
            // ---- epilogue for batch b = bg*8 + bset*4 + (t>>3) ----
            const int b = bg * 8 + bset * 4 + (t >> 3);
            float* obase = out + (((size_t)(b * 8 + v) * 1024) + (size_t)rg * 128) * 128;
            const float* bs = smf + BIAS_OFF;
            #pragma unroll
            for (int mf = 0; mf < 2; mf++) {
                const int r = pr * 32 + mf * 16 + qrow;
                #pragma unroll
                for (int nf = 0; nf < 8; nf++) {
                    const int e0 = n0 + nf * 8 + qcol * 2;
                    float2 lo, hi;
                    lo.x = acc[mf][nf][0] + bs[e0];
                    lo.y = acc[mf][nf][1] + bs[e0 + 1];
                    hi.x = acc[mf][nf][2] + bs[e0];
                    hi.y = acc[mf][nf][3] + bs[e0 + 1];
                    *reinterpret_cast<float2*>(obase + (size_t)r * 128 + e0)       = lo;
                    *reinterpret_cast<float2*>(obase + (size_t)(r + 8) * 128 + e0) = hi;
                    acc[mf][nf][0] = 0.0f; acc[mf][nf][1] = 0.0f;
                    acc[mf][nf][2] = 0.0f; acc[mf][nf][3] = 0.0f;
                }
            }
        }
    }
}

extern "C" void kernel_launch(void* const* d_in, const int* in_sizes, int n_in,
                              void* d_out, int out_size)
{
    const float* x       = (const float*)d_in[0];
    const int*   in_vars = (const int*)d_in[1];
    const float* w       = (const float*)d_in[2];
    const float* bias    = (const float*)d_in[3];
    float*       out     = (float*)d_out;

    cudaFuncSetAttribute(pve_mma_kernel,
                         cudaFuncAttributeMaxDynamicSharedMemorySize, SMEM_BYTES);

    dim3 grid(8, 8, 2);    // (row group, V, batch group) -> 128 persistent CTAs
    pve_mma_kernel<<<grid, THREADS, SMEM_BYTES>>>(x, in_vars, w, bias, out);
}